// round 13
// baseline (speedup 1.0000x reference)
#include <cuda_runtime.h>
#include <cuda_bf16.h>
#include <cstddef>

// ---------------- problem constants ----------------
#define NN 50000
#define NE 10000
#define DD 128
#define NNZI 400000
#define NNZE 80000
#define NNZV 400000
#define TOTIDX (2*NNZI + NNZV + NNZE)   // 1,280,000

static const size_t ND = (size_t)NN * DD;   // 6,400,000
static const size_t ED = (size_t)NE * DD;   // 1,280,000

// ---------------- float scratch (no zeroing needed) ----------------
static const size_t OFF_U     = 0;          // E
static const size_t OFF_T     = ED;         // E
static const size_t OFF_EMA   = 2*ED;       // E
static const size_t OFF_A     = 3*ED;       // E
static const size_t OFF_EW    = 4*ED;       // E
static const size_t OFF_E2    = 5*ED;       // E
static const size_t OFF_E2ACC = 6*ED;       // E
static const size_t OFF_V2    = 7*ED;       // N
static const size_t OFF_V3    = 7*ED + ND;  // N
static const size_t OFF_DW    = 7*ED + 2*ND;          // NE
static const size_t OFF_CNT   = 7*ED + 2*ND + NE;     // NE
static const size_t OFF_WV    = 7*ED + 2*ND + 2*NE;   // NNZV (reordered vmat vals)
static const size_t OFF_WE    = OFF_WV + NNZV;        // NNZE (reordered emat vals)
#define SCRATCH_TOTAL (7*1280000ull + 2*6400000ull + 2*10000ull + 400000ull + 80000ull)
__device__ float g_scratch[SCRATCH_TOTAL];

// ---------------- int scratch: CSR structures ----------------
#define IC_CD 0
#define IC_CS (IC_CD + NE)
#define IC_CV (IC_CS + NN)
#define IC_CE (IC_CV + NN)
#define ICNT_LEN (IC_CE + NE)                 // 120,000 (zeroed each call)
#define IR_D (ICNT_LEN)
#define IR_S (IR_D + NE + 1)
#define IR_V (IR_S + NN + 1)
#define IR_E (IR_V + NN + 1)
#define IQ_D (IR_E + NE + 1)
#define IQ_S (IQ_D + NE)
#define IQ_V (IQ_S + NN)
#define IQ_E (IQ_V + NN)
#define IG_D (IQ_E + NE)
#define IG_S (IG_D + NNZI)
#define IG_V (IG_S + NNZI)
#define IG_E (IG_V + NNZV)
#define ITOTAL (IG_E + NNZE)
__device__ int g_iscr[ITOTAL];

typedef unsigned long long u64;

__device__ __forceinline__ void fma2(u64& d, u64 a, u64 b) {
    asm("fma.rn.f32x2 %0, %1, %2, %0;" : "+l"(d) : "l"(a), "l"(b));
}
__device__ __forceinline__ u64 dup2(float v) {
    u64 r;
    asm("mov.b64 %0, {%1,%1};" : "=l"(r) : "r"(__float_as_uint(v)));
    return r;
}
__device__ __forceinline__ float lo32(u64 v) { return __uint_as_float((unsigned)v); }
__device__ __forceinline__ float hi32(u64 v) { return __uint_as_float((unsigned)(v >> 32)); }

// ================= CSR build =================
__global__ void hist_kernel(const int* __restrict__ inc_dst, const int* __restrict__ inc_src,
                            const int* __restrict__ vmat_rows, const int* __restrict__ emat_rows,
                            int* __restrict__ ib) {
    int i = blockIdx.x * blockDim.x + threadIdx.x;
    if (i < NNZI)                     atomicAdd(&ib[IC_CD + inc_dst[i]], 1);
    else if (i < 2*NNZI)              atomicAdd(&ib[IC_CS + inc_src[i - NNZI]], 1);
    else if (i < 2*NNZI + NNZV)       atomicAdd(&ib[IC_CV + vmat_rows[i - 2*NNZI]], 1);
    else if (i < TOTIDX)              atomicAdd(&ib[IC_CE + emat_rows[i - 2*NNZI - NNZV]], 1);
}

// 4 blocks: exclusive scan -> row_start + cursor; block 0 also emits cnt[] as float.
__global__ __launch_bounds__(1024) void scan4_kernel(int* __restrict__ ib, float* __restrict__ cntf) {
    __shared__ int part[1024];
    int b = blockIdx.x, t = threadIdx.x;
    int cofs, n, rofs, qofs;
    if (b == 0)      { cofs = IC_CD; n = NE; rofs = IR_D; qofs = IQ_D; }
    else if (b == 1) { cofs = IC_CS; n = NN; rofs = IR_S; qofs = IQ_S; }
    else if (b == 2) { cofs = IC_CV; n = NN; rofs = IR_V; qofs = IQ_V; }
    else             { cofs = IC_CE; n = NE; rofs = IR_E; qofs = IQ_E; }
    const int* cnt = ib + cofs;
    int* rs  = ib + rofs;
    int* cur = ib + qofs;
    int chunk = (n + 1023) >> 10;
    int s0 = t * chunk, s = 0;
    for (int k = 0; k < chunk; k++) { int idx = s0 + k; if (idx < n) s += cnt[idx]; }
    part[t] = s;
    __syncthreads();
    for (int off = 1; off < 1024; off <<= 1) {
        int v = (t >= off) ? part[t - off] : 0;
        __syncthreads();
        part[t] += v;
        __syncthreads();
    }
    int run = part[t] - s;   // exclusive prefix
    for (int k = 0; k < chunk; k++) {
        int idx = s0 + k;
        if (idx < n) {
            int c = cnt[idx];
            rs[idx] = run; cur[idx] = run;
            if (b == 0) cntf[idx] = (float)c;
            run += c;
        }
    }
    if (t == 1023) rs[n] = part[1023];
}

// Fully resolve gather targets into segment-ordered arrays.
__global__ void permute_kernel(const int* __restrict__ inc_dst, const int* __restrict__ inc_src,
                               const int* __restrict__ vmat_rows, const int* __restrict__ vmat_cols,
                               const float* __restrict__ vmat_vals,
                               const int* __restrict__ emat_rows, const int* __restrict__ emat_cols,
                               const float* __restrict__ emat_vals,
                               int* __restrict__ ib, float* __restrict__ wV, float* __restrict__ wE) {
    int i = blockIdx.x * blockDim.x + threadIdx.x;
    if (i < NNZI) {
        int p = atomicAdd(&ib[IQ_D + inc_dst[i]], 1);
        ib[IG_D + p] = inc_src[i];
    } else if (i < 2*NNZI) {
        int j = i - NNZI;
        int p = atomicAdd(&ib[IQ_S + inc_src[j]], 1);
        ib[IG_S + p] = inc_dst[j];
    } else if (i < 2*NNZI + NNZV) {
        int j = i - 2*NNZI;
        int p = atomicAdd(&ib[IQ_V + vmat_rows[j]], 1);
        ib[IG_V + p] = vmat_cols[j];
        wV[p] = vmat_vals[j];
    } else if (i < TOTIDX) {
        int j = i - 2*NNZI - NNZV;
        int p = atomicAdd(&ib[IQ_E + emat_rows[j]], 1);
        ib[IG_E + p] = emat_cols[j];
        wE[p] = emat_vals[j];
    }
}

// ================= CSR segment reduce (warp/segment, MLP=4) =================
__global__ __launch_bounds__(256) void csr_reduce_kernel(
    const int* __restrict__ rs, const int* __restrict__ g,
    const float* __restrict__ src, float* __restrict__ dst,
    int nseg, int doRelu) {
    int w = (blockIdx.x * blockDim.x + threadIdx.x) >> 5;
    int lane = threadIdx.x & 31;
    if (w >= nseg) return;
    int j = rs[w], end = rs[w + 1];
    float ax = 0.f, ay = 0.f, az = 0.f, aw = 0.f;
    float bx = 0.f, by = 0.f, bz = 0.f, bw = 0.f;
    for (; j + 4 <= end; j += 4) {
        int g0 = __ldg(g + j), g1 = __ldg(g + j + 1);
        int g2 = __ldg(g + j + 2), g3 = __ldg(g + j + 3);
        float4 x0 = __ldg((const float4*)(src + (size_t)g0 * DD) + lane);
        float4 x1 = __ldg((const float4*)(src + (size_t)g1 * DD) + lane);
        float4 x2 = __ldg((const float4*)(src + (size_t)g2 * DD) + lane);
        float4 x3 = __ldg((const float4*)(src + (size_t)g3 * DD) + lane);
        ax += x0.x + x1.x; ay += x0.y + x1.y; az += x0.z + x1.z; aw += x0.w + x1.w;
        bx += x2.x + x3.x; by += x2.y + x3.y; bz += x2.z + x3.z; bw += x2.w + x3.w;
    }
    for (; j < end; j++) {
        int g0 = __ldg(g + j);
        float4 x0 = __ldg((const float4*)(src + (size_t)g0 * DD) + lane);
        ax += x0.x; ay += x0.y; az += x0.z; aw += x0.w;
    }
    ax += bx; ay += by; az += bz; aw += bw;
    if (doRelu) {
        ax = fmaxf(ax, 0.f); ay = fmaxf(ay, 0.f);
        az = fmaxf(az, 0.f); aw = fmaxf(aw, 0.f);
    }
    *((float4*)(dst + (size_t)w * DD) + lane) = make_float4(ax, ay, az, aw);
}

__global__ __launch_bounds__(256) void csr_reduceW_kernel(
    const int* __restrict__ rs, const int* __restrict__ g, const float* __restrict__ wgt,
    const float* __restrict__ src, float* __restrict__ dst, int nseg) {
    int w = (blockIdx.x * blockDim.x + threadIdx.x) >> 5;
    int lane = threadIdx.x & 31;
    if (w >= nseg) return;
    int j = rs[w], end = rs[w + 1];
    float ax = 0.f, ay = 0.f, az = 0.f, aw = 0.f;
    float bx = 0.f, by = 0.f, bz = 0.f, bw = 0.f;
    for (; j + 4 <= end; j += 4) {
        int g0 = __ldg(g + j), g1 = __ldg(g + j + 1);
        int g2 = __ldg(g + j + 2), g3 = __ldg(g + j + 3);
        float v0 = __ldg(wgt + j), v1 = __ldg(wgt + j + 1);
        float v2 = __ldg(wgt + j + 2), v3 = __ldg(wgt + j + 3);
        float4 x0 = __ldg((const float4*)(src + (size_t)g0 * DD) + lane);
        float4 x1 = __ldg((const float4*)(src + (size_t)g1 * DD) + lane);
        float4 x2 = __ldg((const float4*)(src + (size_t)g2 * DD) + lane);
        float4 x3 = __ldg((const float4*)(src + (size_t)g3 * DD) + lane);
        ax = fmaf(x0.x, v0, fmaf(x1.x, v1, ax));
        ay = fmaf(x0.y, v0, fmaf(x1.y, v1, ay));
        az = fmaf(x0.z, v0, fmaf(x1.z, v1, az));
        aw = fmaf(x0.w, v0, fmaf(x1.w, v1, aw));
        bx = fmaf(x2.x, v2, fmaf(x3.x, v3, bx));
        by = fmaf(x2.y, v2, fmaf(x3.y, v3, by));
        bz = fmaf(x2.z, v2, fmaf(x3.z, v3, bz));
        bw = fmaf(x2.w, v2, fmaf(x3.w, v3, bw));
    }
    for (; j < end; j++) {
        int g0 = __ldg(g + j);
        float v0 = __ldg(wgt + j);
        float4 x0 = __ldg((const float4*)(src + (size_t)g0 * DD) + lane);
        ax = fmaf(x0.x, v0, ax); ay = fmaf(x0.y, v0, ay);
        az = fmaf(x0.z, v0, az); aw = fmaf(x0.w, v0, aw);
    }
    ax += bx; ay += by; az += bz; aw += bw;
    *((float4*)(dst + (size_t)w * DD) + lane) = make_float4(ax, ay, az, aw);
}

__global__ __launch_bounds__(256) void csr_reduceU_kernel(
    const int* __restrict__ rs, const int* __restrict__ g,
    const float* __restrict__ invDV, const float* __restrict__ vfeat,
    float* __restrict__ U, float* __restrict__ dw, int nseg) {
    int w = (blockIdx.x * blockDim.x + threadIdx.x) >> 5;
    int lane = threadIdx.x & 31;
    if (w >= nseg) return;
    int j = rs[w], end = rs[w + 1];
    float ax = 0.f, ay = 0.f, az = 0.f, aw = 0.f, ws = 0.f;
    float bx = 0.f, by = 0.f, bz = 0.f, bw = 0.f;
    for (; j + 4 <= end; j += 4) {
        int g0 = __ldg(g + j), g1 = __ldg(g + j + 1);
        int g2 = __ldg(g + j + 2), g3 = __ldg(g + j + 3);
        float v0 = __ldg(invDV + g0), v1 = __ldg(invDV + g1);
        float v2 = __ldg(invDV + g2), v3 = __ldg(invDV + g3);
        float4 x0 = __ldg((const float4*)(vfeat + (size_t)g0 * DD) + lane);
        float4 x1 = __ldg((const float4*)(vfeat + (size_t)g1 * DD) + lane);
        float4 x2 = __ldg((const float4*)(vfeat + (size_t)g2 * DD) + lane);
        float4 x3 = __ldg((const float4*)(vfeat + (size_t)g3 * DD) + lane);
        ax = fmaf(x0.x, v0, fmaf(x1.x, v1, ax));
        ay = fmaf(x0.y, v0, fmaf(x1.y, v1, ay));
        az = fmaf(x0.z, v0, fmaf(x1.z, v1, az));
        aw = fmaf(x0.w, v0, fmaf(x1.w, v1, aw));
        bx = fmaf(x2.x, v2, fmaf(x3.x, v3, bx));
        by = fmaf(x2.y, v2, fmaf(x3.y, v3, by));
        bz = fmaf(x2.z, v2, fmaf(x3.z, v3, bz));
        bw = fmaf(x2.w, v2, fmaf(x3.w, v3, bw));
        ws += (v0 + v1) + (v2 + v3);
    }
    for (; j < end; j++) {
        int g0 = __ldg(g + j);
        float v0 = __ldg(invDV + g0);
        float4 x0 = __ldg((const float4*)(vfeat + (size_t)g0 * DD) + lane);
        ax = fmaf(x0.x, v0, ax); ay = fmaf(x0.y, v0, ay);
        az = fmaf(x0.z, v0, az); aw = fmaf(x0.w, v0, aw);
        ws += v0;
    }
    ax += bx; ay += by; az += bz; aw += bw;
    *((float4*)(U + (size_t)w * DD) + lane) = make_float4(ax, ay, az, aw);
    if (lane == 0) dw[w] = ws;
}

// ================= Fused 2-part GEMM (R8 BM=64 shape + register prefetch) ======
// C[m,n] = post( sum_p ( (sap.*sbp.*(Ap [+A1b if p==0])) @ Wp.T )[m,n] )
// post: v = acc + (bsa[m]*bsb[m])*bias[n] + Cadd[m,n]; optional relu.
// BM=64, BN=128, BK=16; part p contributes K=128. A2==null -> single part.
__global__ __launch_bounds__(256) void gemm_kernel(
    const float* __restrict__ A1, const float* __restrict__ A1b,
    const float* __restrict__ sa1, const float* __restrict__ sb1,
    const float* __restrict__ W1, int ldW1,
    const float* __restrict__ A2,
    const float* __restrict__ sa2, const float* __restrict__ sb2,
    const float* __restrict__ W2, int ldW2,
    const float* __restrict__ bias, const float* __restrict__ bsa, const float* __restrict__ bsb,
    const float* __restrict__ Cadd, float* __restrict__ C, int M, int doRelu) {
    __shared__ float As[16][64];
    __shared__ float Bs[16][128];
    int m0 = blockIdx.x * 64;
    int tid = threadIdx.x;
    int tm = tid >> 5;
    int tn = tid & 31;
    int nT = A2 ? 16 : 8;

    u64 acc[4][4];
#pragma unroll
    for (int p = 0; p < 4; p++)
#pragma unroll
        for (int j = 0; j < 4; j++) acc[p][j] = 0ull;

    int ra = tid >> 2;            // A-load row 0..63
    int ka = (tid & 3) * 4;       // A-load k offset
    int wn = tid >> 1;            // W rows handled via idx scheme below

    float4 pa;                    // prefetched A
    float4 pw0, pw1;              // prefetched W (2 float4 per thread)

    auto loadTile = [&](int t) {
        int pp = (t >> 3);
        int kk = (t & 7) * 16;
        const float* Ap  = pp ? A2  : A1;
        const float* sap = pp ? sa2 : sa1;
        const float* sbp = pp ? sb2 : sb1;
        const float* Wp  = pp ? W2  : W1;
        int ldW          = pp ? ldW2 : ldW1;
        int gm = m0 + ra;
        pa = make_float4(0.f, 0.f, 0.f, 0.f);
        if (gm < M) {
            pa = *(const float4*)(Ap + (size_t)gm * DD + kk + ka);
            if (!pp && A1b) {
                float4 b = *(const float4*)(A1b + (size_t)gm * DD + kk + ka);
                pa.x += b.x; pa.y += b.y; pa.z += b.z; pa.w += b.w;
            }
            float s = 1.f;
            if (sap) s = sap[gm];
            if (sbp) s *= sbp[gm];
            pa.x *= s; pa.y *= s; pa.z *= s; pa.w *= s;
        }
        int i0 = tid * 2;
        int n0 = i0 >> 2,  kq0 = (i0 & 3) * 4;
        int n1 = (i0 + 1) >> 2, kq1 = ((i0 + 1) & 3) * 4;
        pw0 = *(const float4*)(Wp + (size_t)n0 * ldW + kk + kq0);
        pw1 = *(const float4*)(Wp + (size_t)n1 * ldW + kk + kq1);
    };
    auto storeTile = [&]() {
        As[ka + 0][ra] = pa.x;
        As[ka + 1][ra] = pa.y;
        As[ka + 2][ra] = pa.z;
        As[ka + 3][ra] = pa.w;
        int i0 = tid * 2;
        int n0 = i0 >> 2,  kq0 = (i0 & 3) * 4;
        int n1 = (i0 + 1) >> 2, kq1 = ((i0 + 1) & 3) * 4;
        Bs[kq0 + 0][n0] = pw0.x;
        Bs[kq0 + 1][n0] = pw0.y;
        Bs[kq0 + 2][n0] = pw0.z;
        Bs[kq0 + 3][n0] = pw0.w;
        Bs[kq1 + 0][n1] = pw1.x;
        Bs[kq1 + 1][n1] = pw1.y;
        Bs[kq1 + 2][n1] = pw1.z;
        Bs[kq1 + 3][n1] = pw1.w;
    };

    (void)wn;
    loadTile(0);
    for (int t = 0; t < nT; t++) {
        storeTile();
        __syncthreads();
        if (t + 1 < nT) loadTile(t + 1);   // LDGs in flight during compute
#pragma unroll
        for (int k = 0; k < 16; k++) {
            const u64* ap = (const u64*)&As[k][tm * 8];
            u64 a0 = ap[0], a1 = ap[1], a2 = ap[2], a3 = ap[3];
            float4 bv = *(const float4*)&Bs[k][tn * 4];
            u64 b0 = dup2(bv.x), b1 = dup2(bv.y), b2 = dup2(bv.z), b3 = dup2(bv.w);
            fma2(acc[0][0], a0, b0); fma2(acc[0][1], a0, b1);
            fma2(acc[0][2], a0, b2); fma2(acc[0][3], a0, b3);
            fma2(acc[1][0], a1, b0); fma2(acc[1][1], a1, b1);
            fma2(acc[1][2], a1, b2); fma2(acc[1][3], a1, b3);
            fma2(acc[2][0], a2, b0); fma2(acc[2][1], a2, b1);
            fma2(acc[2][2], a2, b2); fma2(acc[2][3], a2, b3);
            fma2(acc[3][0], a3, b0); fma2(acc[3][1], a3, b1);
            fma2(acc[3][2], a3, b2); fma2(acc[3][3], a3, b3);
        }
        __syncthreads();
    }

    float bvals[4];
#pragma unroll
    for (int j = 0; j < 4; j++) bvals[j] = bias ? bias[tn * 4 + j] : 0.f;

#pragma unroll
    for (int p = 0; p < 4; p++) {
        int mA = m0 + tm * 8 + p * 2;
#pragma unroll
        for (int q = 0; q < 2; q++) {
            int m = mA + q;
            if (m >= M) continue;
            float bs = 1.f;
            if (bias) {
                if (bsa) bs = bsa[m];
                if (bsb) bs *= bsb[m];
            }
            float4 ca = make_float4(0.f, 0.f, 0.f, 0.f);
            if (Cadd) ca = *(const float4*)(Cadd + (size_t)m * DD + tn * 4);
            float r0 = q ? hi32(acc[p][0]) : lo32(acc[p][0]);
            float r1 = q ? hi32(acc[p][1]) : lo32(acc[p][1]);
            float r2 = q ? hi32(acc[p][2]) : lo32(acc[p][2]);
            float r3 = q ? hi32(acc[p][3]) : lo32(acc[p][3]);
            float v0 = r0 + bs * bvals[0] + ca.x;
            float v1 = r1 + bs * bvals[1] + ca.y;
            float v2 = r2 + bs * bvals[2] + ca.z;
            float v3 = r3 + bs * bvals[3] + ca.w;
            if (doRelu) {
                v0 = fmaxf(v0, 0.f); v1 = fmaxf(v1, 0.f);
                v2 = fmaxf(v2, 0.f); v3 = fmaxf(v3, 0.f);
            }
            *(float4*)(C + (size_t)m * DD + tn * 4) = make_float4(v0, v1, v2, v3);
        }
    }
}

// ---------------- host side ----------------
static inline int seg_grid(int nseg) { return (nseg + 7) / 8; }

static cudaStream_t g_s1 = nullptr;
static cudaEvent_t g_eFork = nullptr, g_eB = nullptr;

extern "C" void kernel_launch(void* const* d_in, const int* in_sizes, int n_in,
                              void* d_out, int out_size) {
    const float* vfeat   = (const float*)d_in[0];
    const float* efeat   = (const float*)d_in[1];
    const float* invDV   = (const float*)d_in[2];
    const float* invDE   = (const float*)d_in[3];
    const int*   inc_src = (const int*)d_in[4];
    const int*   inc_dst = (const int*)d_in[5];
    const int*   emat_rows = (const int*)d_in[6];
    const int*   emat_cols = (const int*)d_in[7];
    const float* emat_vals = (const float*)d_in[8];
    const int*   vmat_rows = (const int*)d_in[9];
    const int*   vmat_cols = (const int*)d_in[10];
    const float* vmat_vals = (const float*)d_in[11];
    const float* Wv      = (const float*)d_in[12];
    const float* We      = (const float*)d_in[13];
    const float* psi1_W  = (const float*)d_in[14];
    const float* psi1_b  = (const float*)d_in[15];
    const float* psi2_W  = (const float*)d_in[16];
    const float* psi2_b  = (const float*)d_in[17];

    if (!g_s1) {
        cudaStreamCreateWithFlags(&g_s1, cudaStreamNonBlocking);
        cudaEventCreateWithFlags(&g_eFork, cudaEventDisableTiming);
        cudaEventCreateWithFlags(&g_eB,    cudaEventDisableTiming);
    }

    float* base = nullptr;
    cudaGetSymbolAddress((void**)&base, g_scratch);
    int* ib = nullptr;
    cudaGetSymbolAddress((void**)&ib, g_iscr);

    float* U     = base + OFF_U;
    float* T     = base + OFF_T;
    float* emA   = base + OFF_EMA;
    float* A     = base + OFF_A;
    float* ew    = base + OFF_EW;
    float* e2    = base + OFF_E2;
    float* e2acc = base + OFF_E2ACC;
    float* v2    = base + OFF_V2;
    float* v3    = base + OFF_V3;
    float* dw    = base + OFF_DW;
    float* cnt   = base + OFF_CNT;
    float* wV    = base + OFF_WV;
    float* wE    = base + OFF_WE;

    float* vout = (float*)d_out;               // [NN,128]
    float* eout = vout + ND;                   // [NE,128]

    const int GG = (NE + 63) / 64;             // 157

    // ===== CSR build (stream 0) =====
    cudaMemsetAsync(ib, 0, ICNT_LEN * sizeof(int));
    hist_kernel<<<(TOTIDX + 255) / 256, 256>>>(inc_dst, inc_src, vmat_rows, emat_rows, ib);
    scan4_kernel<<<4, 1024>>>(ib, cnt);
    permute_kernel<<<(TOTIDX + 255) / 256, 256>>>(inc_dst, inc_src,
                                                  vmat_rows, vmat_cols, vmat_vals,
                                                  emat_rows, emat_cols, emat_vals,
                                                  ib, wV, wE);

    // ---- fork stream 1 ----
    cudaEventRecord(g_eFork, 0);
    cudaStreamWaitEvent(g_s1, g_eFork, 0);

    // ===== stream 1 (chain B): pure reduces =====
    csr_reduce_kernel<<<seg_grid(NN), 256, 0, g_s1>>>(ib + IR_S, ib + IG_S, efeat, v2, NN, 0);
    csr_reduceW_kernel<<<seg_grid(NN), 256, 0, g_s1>>>(ib + IR_V, ib + IG_V, wV, v2, v3, NN);
    csr_reduce_kernel<<<seg_grid(NE), 256, 0, g_s1>>>(ib + IR_D, ib + IG_D, v3, e2acc, NE, 0);
    cudaEventRecord(g_eB, g_s1);

    // ===== stream 0 (chain A) =====
    // U[e] = sum invDV[src]*vfeat[src]; dw[e] = sum invDV[src]
    csr_reduceU_kernel<<<seg_grid(NE), 256>>>(ib + IR_D, ib + IG_D, invDV, vfeat, U, dw, NE);
    // A = (dw.*efeat)@W1e.T + U@W1v.T + dw*b1   (fused K=256)
    gemm_kernel<<<GG, 256>>>(efeat, nullptr, dw, nullptr, psi1_W + 128, 256,
                             U, nullptr, nullptr, psi1_W, 256,
                             psi1_b, dw, nullptr, nullptr, A, NE, 0);
    // emA = emat @ A
    csr_reduceW_kernel<<<seg_grid(NE), 256>>>(ib + IR_E, ib + IG_E, wE, A, emA, NE);
    // ew = (emA + efeat) @ Wv.T   (single part, A1b pre-add)
    gemm_kernel<<<GG, 256>>>(emA, efeat, nullptr, nullptr, Wv, 128,
                             nullptr, nullptr, nullptr, nullptr, 0,
                             nullptr, nullptr, nullptr, nullptr, ew, NE, 0);
    // vout[n] = relu( sum_{inc of n} ew[dst] )
    csr_reduce_kernel<<<seg_grid(NN), 256>>>(ib + IR_S, ib + IG_S, ew, vout, NN, 1);
    // T[e] = sum_{inc of e} vout[src]
    csr_reduce_kernel<<<seg_grid(NE), 256>>>(ib + IR_D, ib + IG_D, vout, T, NE, 0);
    // join chain B; e2 = (invDE.*T)@W2v.T + (invDE.*cnt.*efeat)@W2e.T + invDE*cnt*b2 + e2acc
    cudaStreamWaitEvent(0, g_eB, 0);
    gemm_kernel<<<GG, 256>>>(T, nullptr, invDE, nullptr, psi2_W, 256,
                             efeat, invDE, cnt, psi2_W + 128, 256,
                             psi2_b, invDE, cnt, e2acc, e2, NE, 0);
    // eout = relu(e2 @ We.T)
    gemm_kernel<<<GG, 256>>>(e2, nullptr, nullptr, nullptr, We, 128,
                             nullptr, nullptr, nullptr, nullptr, 0,
                             nullptr, nullptr, nullptr, nullptr, eout, NE, 1);
}

// round 14
// speedup vs baseline: 1.2023x; 1.2023x over previous
#include <cuda_runtime.h>
#include <cuda_bf16.h>
#include <cstddef>

// ---------------- problem constants ----------------
#define NN 50000
#define NE 10000
#define DD 128
#define NNZI 400000
#define NNZE 80000
#define NNZV 400000
#define TOTIDX (2*NNZI + NNZV + NNZE)   // 1,280,000

static const size_t ND = (size_t)NN * DD;   // 6,400,000
static const size_t ED = (size_t)NE * DD;   // 1,280,000

// ---------------- float scratch (no zeroing needed) ----------------
static const size_t OFF_U     = 0;          // E
static const size_t OFF_T     = ED;         // E
static const size_t OFF_EMA   = 2*ED;       // E
static const size_t OFF_A1    = 3*ED;       // E
static const size_t OFF_A2    = 4*ED;       // E
static const size_t OFF_EW    = 5*ED;       // E
static const size_t OFF_E2ACC = 6*ED;       // E
static const size_t OFF_P1    = 7*ED;       // E
static const size_t OFF_P     = 8*ED;       // E
static const size_t OFF_V2    = 9*ED;       // N
static const size_t OFF_V3    = 9*ED + ND;  // N
static const size_t OFF_DW    = 9*ED + 2*ND;            // NE
static const size_t OFF_CNT   = 9*ED + 2*ND + NE;       // NE
static const size_t OFF_IDC   = 9*ED + 2*ND + 2*NE;     // NE  (invDE*cnt)
static const size_t OFF_WV    = 9*ED + 2*ND + 3*NE;     // NNZV (reordered vmat vals)
static const size_t OFF_WE    = OFF_WV + NNZV;          // NNZE (reordered emat vals)
static const size_t OFF_WCV   = OFF_WE + NNZE;          // 16384 (We@W2v, [n][k])
static const size_t OFF_WCE   = OFF_WCV + 16384;        // 16384 (We@W2e, [n][k])
static const size_t OFF_BC    = OFF_WCE + 16384;        // 128   (We@b2)
#define SCRATCH_TOTAL (9*1280000ull + 2*6400000ull + 3*10000ull + 400000ull + 80000ull + 33024ull)
__device__ float g_scratch[SCRATCH_TOTAL];

// ---------------- int scratch: CSR structures ----------------
#define IC_CD 0
#define IC_CS (IC_CD + NE)
#define IC_CV (IC_CS + NN)
#define IC_CE (IC_CV + NN)
#define ICNT_LEN (IC_CE + NE)                 // 120,000 (zeroed each call)
#define IR_D (ICNT_LEN)
#define IR_S (IR_D + NE + 1)
#define IR_V (IR_S + NN + 1)
#define IR_E (IR_V + NN + 1)
#define IQ_D (IR_E + NE + 1)
#define IQ_S (IQ_D + NE)
#define IQ_V (IQ_S + NN)
#define IQ_E (IQ_V + NN)
#define IG_D (IQ_E + NE)
#define IG_S (IG_D + NNZI)
#define IG_V (IG_S + NNZI)
#define IG_E (IG_V + NNZV)
#define ITOTAL (IG_E + NNZE)
__device__ int g_iscr[ITOTAL];

typedef unsigned long long u64;

__device__ __forceinline__ void fma2(u64& d, u64 a, u64 b) {
    asm("fma.rn.f32x2 %0, %1, %2, %0;" : "+l"(d) : "l"(a), "l"(b));
}
__device__ __forceinline__ u64 dup2(float v) {
    u64 r;
    asm("mov.b64 %0, {%1,%1};" : "=l"(r) : "r"(__float_as_uint(v)));
    return r;
}
__device__ __forceinline__ float lo32(u64 v) { return __uint_as_float((unsigned)v); }
__device__ __forceinline__ float hi32(u64 v) { return __uint_as_float((unsigned)(v >> 32)); }

// ================= CSR build =================
__global__ void hist_kernel(const int* __restrict__ inc_dst, const int* __restrict__ inc_src,
                            const int* __restrict__ vmat_rows, const int* __restrict__ emat_rows,
                            int* __restrict__ ib) {
    int i = blockIdx.x * blockDim.x + threadIdx.x;
    if (i < NNZI)                     atomicAdd(&ib[IC_CD + inc_dst[i]], 1);
    else if (i < 2*NNZI)              atomicAdd(&ib[IC_CS + inc_src[i - NNZI]], 1);
    else if (i < 2*NNZI + NNZV)       atomicAdd(&ib[IC_CV + vmat_rows[i - 2*NNZI]], 1);
    else if (i < TOTIDX)              atomicAdd(&ib[IC_CE + emat_rows[i - 2*NNZI - NNZV]], 1);
}

// 4 blocks: exclusive scan -> row_start + cursor; block 0 also emits cnt[] as float.
__global__ __launch_bounds__(1024) void scan4_kernel(int* __restrict__ ib, float* __restrict__ cntf) {
    __shared__ int part[1024];
    int b = blockIdx.x, t = threadIdx.x;
    int cofs, n, rofs, qofs;
    if (b == 0)      { cofs = IC_CD; n = NE; rofs = IR_D; qofs = IQ_D; }
    else if (b == 1) { cofs = IC_CS; n = NN; rofs = IR_S; qofs = IQ_S; }
    else if (b == 2) { cofs = IC_CV; n = NN; rofs = IR_V; qofs = IQ_V; }
    else             { cofs = IC_CE; n = NE; rofs = IR_E; qofs = IQ_E; }
    const int* cnt = ib + cofs;
    int* rs  = ib + rofs;
    int* cur = ib + qofs;
    int chunk = (n + 1023) >> 10;
    int s0 = t * chunk, s = 0;
    for (int k = 0; k < chunk; k++) { int idx = s0 + k; if (idx < n) s += cnt[idx]; }
    part[t] = s;
    __syncthreads();
    for (int off = 1; off < 1024; off <<= 1) {
        int v = (t >= off) ? part[t - off] : 0;
        __syncthreads();
        part[t] += v;
        __syncthreads();
    }
    int run = part[t] - s;   // exclusive prefix
    for (int k = 0; k < chunk; k++) {
        int idx = s0 + k;
        if (idx < n) {
            int c = cnt[idx];
            rs[idx] = run; cur[idx] = run;
            if (b == 0) cntf[idx] = (float)c;
            run += c;
        }
    }
    if (t == 1023) rs[n] = part[1023];
}

// Fully resolve gather targets into segment-ordered arrays.
__global__ void permute_kernel(const int* __restrict__ inc_dst, const int* __restrict__ inc_src,
                               const int* __restrict__ vmat_rows, const int* __restrict__ vmat_cols,
                               const float* __restrict__ vmat_vals,
                               const int* __restrict__ emat_rows, const int* __restrict__ emat_cols,
                               const float* __restrict__ emat_vals,
                               int* __restrict__ ib, float* __restrict__ wV, float* __restrict__ wE) {
    int i = blockIdx.x * blockDim.x + threadIdx.x;
    if (i < NNZI) {
        int p = atomicAdd(&ib[IQ_D + inc_dst[i]], 1);
        ib[IG_D + p] = inc_src[i];
    } else if (i < 2*NNZI) {
        int j = i - NNZI;
        int p = atomicAdd(&ib[IQ_S + inc_src[j]], 1);
        ib[IG_S + p] = inc_dst[j];
    } else if (i < 2*NNZI + NNZV) {
        int j = i - 2*NNZI;
        int p = atomicAdd(&ib[IQ_V + vmat_rows[j]], 1);
        ib[IG_V + p] = vmat_cols[j];
        wV[p] = vmat_vals[j];
    } else if (i < TOTIDX) {
        int j = i - 2*NNZI - NNZV;
        int p = atomicAdd(&ib[IQ_E + emat_rows[j]], 1);
        ib[IG_E + p] = emat_cols[j];
        wE[p] = emat_vals[j];
    }
}

// ============ weight composition: WcV = We@W2v, WcE = We@W2e, bc = We@b2 ========
// Also invDEcnt[e] = invDE[e]*cnt[e]. Stored [n][k] row-major for the gemm W arg.
__global__ void wcomp_kernel(const float* __restrict__ We, const float* __restrict__ psi2_W,
                             const float* __restrict__ psi2_b,
                             const float* __restrict__ invDE, const float* __restrict__ cnt,
                             float* __restrict__ WcV, float* __restrict__ WcE,
                             float* __restrict__ bc, float* __restrict__ idc) {
    int i = blockIdx.x * blockDim.x + threadIdx.x;
    if (i < 16384) {
        int n = i >> 7, k = i & 127;
        float s = 0.f;
#pragma unroll 8
        for (int j = 0; j < 128; j++) s = fmaf(We[n * 128 + j], psi2_W[j * 256 + k], s);
        WcV[n * 128 + k] = s;
    } else if (i < 32768) {
        int t = i - 16384;
        int n = t >> 7, k = t & 127;
        float s = 0.f;
#pragma unroll 8
        for (int j = 0; j < 128; j++) s = fmaf(We[n * 128 + j], psi2_W[j * 256 + 128 + k], s);
        WcE[n * 128 + k] = s;
    } else if (i < 32896) {
        int n = i - 32768;
        float s = 0.f;
#pragma unroll 8
        for (int j = 0; j < 128; j++) s = fmaf(We[n * 128 + j], psi2_b[j], s);
        bc[n] = s;
    }
    if (i < NE) idc[i] = invDE[i] * cnt[i];
}

// ================= CSR segment reduce (warp/segment, MLP=4) =================
__global__ __launch_bounds__(256) void csr_reduce_kernel(
    const int* __restrict__ rs, const int* __restrict__ g,
    const float* __restrict__ src, float* __restrict__ dst,
    int nseg, int doRelu) {
    int w = (blockIdx.x * blockDim.x + threadIdx.x) >> 5;
    int lane = threadIdx.x & 31;
    if (w >= nseg) return;
    int j = rs[w], end = rs[w + 1];
    float ax = 0.f, ay = 0.f, az = 0.f, aw = 0.f;
    float bx = 0.f, by = 0.f, bz = 0.f, bw = 0.f;
    for (; j + 4 <= end; j += 4) {
        int g0 = __ldg(g + j), g1 = __ldg(g + j + 1);
        int g2 = __ldg(g + j + 2), g3 = __ldg(g + j + 3);
        float4 x0 = __ldg((const float4*)(src + (size_t)g0 * DD) + lane);
        float4 x1 = __ldg((const float4*)(src + (size_t)g1 * DD) + lane);
        float4 x2 = __ldg((const float4*)(src + (size_t)g2 * DD) + lane);
        float4 x3 = __ldg((const float4*)(src + (size_t)g3 * DD) + lane);
        ax += x0.x + x1.x; ay += x0.y + x1.y; az += x0.z + x1.z; aw += x0.w + x1.w;
        bx += x2.x + x3.x; by += x2.y + x3.y; bz += x2.z + x3.z; bw += x2.w + x3.w;
    }
    for (; j < end; j++) {
        int g0 = __ldg(g + j);
        float4 x0 = __ldg((const float4*)(src + (size_t)g0 * DD) + lane);
        ax += x0.x; ay += x0.y; az += x0.z; aw += x0.w;
    }
    ax += bx; ay += by; az += bz; aw += bw;
    if (doRelu) {
        ax = fmaxf(ax, 0.f); ay = fmaxf(ay, 0.f);
        az = fmaxf(az, 0.f); aw = fmaxf(aw, 0.f);
    }
    *((float4*)(dst + (size_t)w * DD) + lane) = make_float4(ax, ay, az, aw);
}

__global__ __launch_bounds__(256) void csr_reduceW_kernel(
    const int* __restrict__ rs, const int* __restrict__ g, const float* __restrict__ wgt,
    const float* __restrict__ src, float* __restrict__ dst, int nseg) {
    int w = (blockIdx.x * blockDim.x + threadIdx.x) >> 5;
    int lane = threadIdx.x & 31;
    if (w >= nseg) return;
    int j = rs[w], end = rs[w + 1];
    float ax = 0.f, ay = 0.f, az = 0.f, aw = 0.f;
    float bx = 0.f, by = 0.f, bz = 0.f, bw = 0.f;
    for (; j + 4 <= end; j += 4) {
        int g0 = __ldg(g + j), g1 = __ldg(g + j + 1);
        int g2 = __ldg(g + j + 2), g3 = __ldg(g + j + 3);
        float v0 = __ldg(wgt + j), v1 = __ldg(wgt + j + 1);
        float v2 = __ldg(wgt + j + 2), v3 = __ldg(wgt + j + 3);
        float4 x0 = __ldg((const float4*)(src + (size_t)g0 * DD) + lane);
        float4 x1 = __ldg((const float4*)(src + (size_t)g1 * DD) + lane);
        float4 x2 = __ldg((const float4*)(src + (size_t)g2 * DD) + lane);
        float4 x3 = __ldg((const float4*)(src + (size_t)g3 * DD) + lane);
        ax = fmaf(x0.x, v0, fmaf(x1.x, v1, ax));
        ay = fmaf(x0.y, v0, fmaf(x1.y, v1, ay));
        az = fmaf(x0.z, v0, fmaf(x1.z, v1, az));
        aw = fmaf(x0.w, v0, fmaf(x1.w, v1, aw));
        bx = fmaf(x2.x, v2, fmaf(x3.x, v3, bx));
        by = fmaf(x2.y, v2, fmaf(x3.y, v3, by));
        bz = fmaf(x2.z, v2, fmaf(x3.z, v3, bz));
        bw = fmaf(x2.w, v2, fmaf(x3.w, v3, bw));
    }
    for (; j < end; j++) {
        int g0 = __ldg(g + j);
        float v0 = __ldg(wgt + j);
        float4 x0 = __ldg((const float4*)(src + (size_t)g0 * DD) + lane);
        ax = fmaf(x0.x, v0, ax); ay = fmaf(x0.y, v0, ay);
        az = fmaf(x0.z, v0, az); aw = fmaf(x0.w, v0, aw);
    }
    ax += bx; ay += by; az += bz; aw += bw;
    *((float4*)(dst + (size_t)w * DD) + lane) = make_float4(ax, ay, az, aw);
}

// dual-source weighted reduce: dst[s,:] = sum_j wgt[j] * (srcA[g[j],:] + srcB[g[j],:])
__global__ __launch_bounds__(256) void csr_reduceW2_kernel(
    const int* __restrict__ rs, const int* __restrict__ g, const float* __restrict__ wgt,
    const float* __restrict__ srcA, const float* __restrict__ srcB,
    float* __restrict__ dst, int nseg) {
    int w = (blockIdx.x * blockDim.x + threadIdx.x) >> 5;
    int lane = threadIdx.x & 31;
    if (w >= nseg) return;
    int j = rs[w], end = rs[w + 1];
    float ax = 0.f, ay = 0.f, az = 0.f, aw = 0.f;
    for (; j + 2 <= end; j += 2) {
        int g0 = __ldg(g + j), g1 = __ldg(g + j + 1);
        float v0 = __ldg(wgt + j), v1 = __ldg(wgt + j + 1);
        float4 a0 = __ldg((const float4*)(srcA + (size_t)g0 * DD) + lane);
        float4 b0 = __ldg((const float4*)(srcB + (size_t)g0 * DD) + lane);
        float4 a1 = __ldg((const float4*)(srcA + (size_t)g1 * DD) + lane);
        float4 b1 = __ldg((const float4*)(srcB + (size_t)g1 * DD) + lane);
        ax = fmaf(a0.x + b0.x, v0, fmaf(a1.x + b1.x, v1, ax));
        ay = fmaf(a0.y + b0.y, v0, fmaf(a1.y + b1.y, v1, ay));
        az = fmaf(a0.z + b0.z, v0, fmaf(a1.z + b1.z, v1, az));
        aw = fmaf(a0.w + b0.w, v0, fmaf(a1.w + b1.w, v1, aw));
    }
    if (j < end) {
        int g0 = __ldg(g + j);
        float v0 = __ldg(wgt + j);
        float4 a0 = __ldg((const float4*)(srcA + (size_t)g0 * DD) + lane);
        float4 b0 = __ldg((const float4*)(srcB + (size_t)g0 * DD) + lane);
        ax = fmaf(a0.x + b0.x, v0, ax); ay = fmaf(a0.y + b0.y, v0, ay);
        az = fmaf(a0.z + b0.z, v0, az); aw = fmaf(a0.w + b0.w, v0, aw);
    }
    *((float4*)(dst + (size_t)w * DD) + lane) = make_float4(ax, ay, az, aw);
}

__global__ __launch_bounds__(256) void csr_reduceU_kernel(
    const int* __restrict__ rs, const int* __restrict__ g,
    const float* __restrict__ invDV, const float* __restrict__ vfeat,
    float* __restrict__ U, float* __restrict__ dw, int nseg) {
    int w = (blockIdx.x * blockDim.x + threadIdx.x) >> 5;
    int lane = threadIdx.x & 31;
    if (w >= nseg) return;
    int j = rs[w], end = rs[w + 1];
    float ax = 0.f, ay = 0.f, az = 0.f, aw = 0.f, ws = 0.f;
    float bx = 0.f, by = 0.f, bz = 0.f, bw = 0.f;
    for (; j + 4 <= end; j += 4) {
        int g0 = __ldg(g + j), g1 = __ldg(g + j + 1);
        int g2 = __ldg(g + j + 2), g3 = __ldg(g + j + 3);
        float v0 = __ldg(invDV + g0), v1 = __ldg(invDV + g1);
        float v2 = __ldg(invDV + g2), v3 = __ldg(invDV + g3);
        float4 x0 = __ldg((const float4*)(vfeat + (size_t)g0 * DD) + lane);
        float4 x1 = __ldg((const float4*)(vfeat + (size_t)g1 * DD) + lane);
        float4 x2 = __ldg((const float4*)(vfeat + (size_t)g2 * DD) + lane);
        float4 x3 = __ldg((const float4*)(vfeat + (size_t)g3 * DD) + lane);
        ax = fmaf(x0.x, v0, fmaf(x1.x, v1, ax));
        ay = fmaf(x0.y, v0, fmaf(x1.y, v1, ay));
        az = fmaf(x0.z, v0, fmaf(x1.z, v1, az));
        aw = fmaf(x0.w, v0, fmaf(x1.w, v1, aw));
        bx = fmaf(x2.x, v2, fmaf(x3.x, v3, bx));
        by = fmaf(x2.y, v2, fmaf(x3.y, v3, by));
        bz = fmaf(x2.z, v2, fmaf(x3.z, v3, bz));
        bw = fmaf(x2.w, v2, fmaf(x3.w, v3, bw));
        ws += (v0 + v1) + (v2 + v3);
    }
    for (; j < end; j++) {
        int g0 = __ldg(g + j);
        float v0 = __ldg(invDV + g0);
        float4 x0 = __ldg((const float4*)(vfeat + (size_t)g0 * DD) + lane);
        ax = fmaf(x0.x, v0, ax); ay = fmaf(x0.y, v0, ay);
        az = fmaf(x0.z, v0, az); aw = fmaf(x0.w, v0, aw);
        ws += v0;
    }
    ax += bx; ay += by; az += bz; aw += bw;
    *((float4*)(U + (size_t)w * DD) + lane) = make_float4(ax, ay, az, aw);
    if (lane == 0) dw[w] = ws;
}

// ================= GEMM (verbatim R8): C = post( (A+A2) @ W.T ), f32x2 math ====
// post: v = (acc + bias[n] + Cprev[m,n]) * rowScale[m] + Cadd[m,n]; optional relu.
__global__ __launch_bounds__(256) void gemm_kernel(
    const float* __restrict__ A, const float* __restrict__ A2,
    const float* __restrict__ W, int ldW,
    const float* __restrict__ bias, const float* __restrict__ rowScale,
    const float* __restrict__ Cprev, const float* __restrict__ Cadd,
    float* __restrict__ C, int M, int doRelu) {
    __shared__ float As[16][64];
    __shared__ float Bs[16][128];
    int m0 = blockIdx.x * 64;
    int tid = threadIdx.x;
    int tm = tid >> 5;
    int tn = tid & 31;

    u64 acc[4][4];
#pragma unroll
    for (int p = 0; p < 4; p++)
#pragma unroll
        for (int j = 0; j < 4; j++) acc[p][j] = 0ull;

    int ra = tid >> 2;
    int ka = (tid & 3) * 4;

    for (int kk = 0; kk < 128; kk += 16) {
        float4 av = make_float4(0.f, 0.f, 0.f, 0.f);
        int gm = m0 + ra;
        if (gm < M) {
            av = *(const float4*)(A + (size_t)gm * DD + kk + ka);
            if (A2) {
                float4 a2 = *(const float4*)(A2 + (size_t)gm * DD + kk + ka);
                av.x += a2.x; av.y += a2.y; av.z += a2.z; av.w += a2.w;
            }
        }
        As[ka + 0][ra] = av.x;
        As[ka + 1][ra] = av.y;
        As[ka + 2][ra] = av.z;
        As[ka + 3][ra] = av.w;
#pragma unroll
        for (int i = 0; i < 2; i++) {
            int idx = tid * 2 + i;
            int n = idx >> 2;
            int kq = (idx & 3) * 4;
            float4 wv = *(const float4*)(W + (size_t)n * ldW + kk + kq);
            Bs[kq + 0][n] = wv.x;
            Bs[kq + 1][n] = wv.y;
            Bs[kq + 2][n] = wv.z;
            Bs[kq + 3][n] = wv.w;
        }
        __syncthreads();
#pragma unroll
        for (int k = 0; k < 16; k++) {
            const u64* ap = (const u64*)&As[k][tm * 8];
            u64 a0 = ap[0], a1 = ap[1], a2 = ap[2], a3 = ap[3];
            float4 bv = *(const float4*)&Bs[k][tn * 4];
            u64 b0 = dup2(bv.x), b1 = dup2(bv.y), b2 = dup2(bv.z), b3 = dup2(bv.w);
            fma2(acc[0][0], a0, b0); fma2(acc[0][1], a0, b1);
            fma2(acc[0][2], a0, b2); fma2(acc[0][3], a0, b3);
            fma2(acc[1][0], a1, b0); fma2(acc[1][1], a1, b1);
            fma2(acc[1][2], a1, b2); fma2(acc[1][3], a1, b3);
            fma2(acc[2][0], a2, b0); fma2(acc[2][1], a2, b1);
            fma2(acc[2][2], a2, b2); fma2(acc[2][3], a2, b3);
            fma2(acc[3][0], a3, b0); fma2(acc[3][1], a3, b1);
            fma2(acc[3][2], a3, b2); fma2(acc[3][3], a3, b3);
        }
        __syncthreads();
    }

    float bvals[4];
#pragma unroll
    for (int j = 0; j < 4; j++) bvals[j] = bias ? bias[tn * 4 + j] : 0.f;

#pragma unroll
    for (int p = 0; p < 4; p++) {
        int mA = m0 + tm * 8 + p * 2;
#pragma unroll
        for (int q = 0; q < 2; q++) {
            int m = mA + q;
            if (m >= M) continue;
            float rs = rowScale ? rowScale[m] : 1.f;
            float4 cp = make_float4(0.f, 0.f, 0.f, 0.f);
            if (Cprev) cp = *(const float4*)(Cprev + (size_t)m * DD + tn * 4);
            float4 ca = make_float4(0.f, 0.f, 0.f, 0.f);
            if (Cadd) ca = *(const float4*)(Cadd + (size_t)m * DD + tn * 4);
            float r0 = q ? hi32(acc[p][0]) : lo32(acc[p][0]);
            float r1 = q ? hi32(acc[p][1]) : lo32(acc[p][1]);
            float r2 = q ? hi32(acc[p][2]) : lo32(acc[p][2]);
            float r3 = q ? hi32(acc[p][3]) : lo32(acc[p][3]);
            float v0 = (r0 + bvals[0] + cp.x) * rs + ca.x;
            float v1 = (r1 + bvals[1] + cp.y) * rs + ca.y;
            float v2 = (r2 + bvals[2] + cp.z) * rs + ca.z;
            float v3 = (r3 + bvals[3] + cp.w) * rs + ca.w;
            if (doRelu) {
                v0 = fmaxf(v0, 0.f); v1 = fmaxf(v1, 0.f);
                v2 = fmaxf(v2, 0.f); v3 = fmaxf(v3, 0.f);
            }
            *(float4*)(C + (size_t)m * DD + tn * 4) = make_float4(v0, v1, v2, v3);
        }
    }
}

// ---------------- host side ----------------
static inline int seg_grid(int nseg) { return (nseg + 7) / 8; }

static cudaStream_t g_s1 = nullptr, g_s2 = nullptr;
static cudaEvent_t g_eFork = nullptr, g_eU = nullptr, g_eA2 = nullptr,
                   g_eP1 = nullptr, g_eB = nullptr;

extern "C" void kernel_launch(void* const* d_in, const int* in_sizes, int n_in,
                              void* d_out, int out_size) {
    const float* vfeat   = (const float*)d_in[0];
    const float* efeat   = (const float*)d_in[1];
    const float* invDV   = (const float*)d_in[2];
    const float* invDE   = (const float*)d_in[3];
    const int*   inc_src = (const int*)d_in[4];
    const int*   inc_dst = (const int*)d_in[5];
    const int*   emat_rows = (const int*)d_in[6];
    const int*   emat_cols = (const int*)d_in[7];
    const float* emat_vals = (const float*)d_in[8];
    const int*   vmat_rows = (const int*)d_in[9];
    const int*   vmat_cols = (const int*)d_in[10];
    const float* vmat_vals = (const float*)d_in[11];
    const float* Wv      = (const float*)d_in[12];
    const float* We      = (const float*)d_in[13];
    const float* psi1_W  = (const float*)d_in[14];
    const float* psi1_b  = (const float*)d_in[15];
    const float* psi2_W  = (const float*)d_in[16];
    const float* psi2_b  = (const float*)d_in[17];

    if (!g_s1) {
        cudaStreamCreateWithFlags(&g_s1, cudaStreamNonBlocking);
        cudaStreamCreateWithFlags(&g_s2, cudaStreamNonBlocking);
        cudaEventCreateWithFlags(&g_eFork, cudaEventDisableTiming);
        cudaEventCreateWithFlags(&g_eU,    cudaEventDisableTiming);
        cudaEventCreateWithFlags(&g_eA2,   cudaEventDisableTiming);
        cudaEventCreateWithFlags(&g_eP1,   cudaEventDisableTiming);
        cudaEventCreateWithFlags(&g_eB,    cudaEventDisableTiming);
    }

    float* base = nullptr;
    cudaGetSymbolAddress((void**)&base, g_scratch);
    int* ib = nullptr;
    cudaGetSymbolAddress((void**)&ib, g_iscr);

    float* U     = base + OFF_U;
    float* T     = base + OFF_T;
    float* emA   = base + OFF_EMA;
    float* A1    = base + OFF_A1;
    float* A2b   = base + OFF_A2;
    float* ew    = base + OFF_EW;
    float* e2acc = base + OFF_E2ACC;
    float* P1    = base + OFF_P1;
    float* P     = base + OFF_P;
    float* v2    = base + OFF_V2;
    float* v3    = base + OFF_V3;
    float* dw    = base + OFF_DW;
    float* cnt   = base + OFF_CNT;
    float* idc   = base + OFF_IDC;
    float* wV    = base + OFF_WV;
    float* wE    = base + OFF_WE;
    float* WcV   = base + OFF_WCV;
    float* WcE   = base + OFF_WCE;
    float* bc    = base + OFF_BC;

    float* vout = (float*)d_out;               // [NN,128]
    float* eout = vout + ND;                   // [NE,128]

    const int GG = (NE + 63) / 64;             // 157

    // ===== CSR build (stream 0) =====
    cudaMemsetAsync(ib, 0, ICNT_LEN * sizeof(int));
    hist_kernel<<<(TOTIDX + 255) / 256, 256>>>(inc_dst, inc_src, vmat_rows, emat_rows, ib);
    scan4_kernel<<<4, 1024>>>(ib, cnt);
    permute_kernel<<<(TOTIDX + 255) / 256, 256>>>(inc_dst, inc_src,
                                                  vmat_rows, vmat_cols, vmat_vals,
                                                  emat_rows, emat_cols, emat_vals,
                                                  ib, wV, wE);

    // ---- fork streams 1 & 2 ----
    cudaEventRecord(g_eFork, 0);
    cudaStreamWaitEvent(g_s1, g_eFork, 0);
    cudaStreamWaitEvent(g_s2, g_eFork, 0);

    // ===== stream 2: weight composition, then A2 gemm, then P1 gemm =====
    wcomp_kernel<<<129, 256, 0, g_s2>>>(We, psi2_W, psi2_b, invDE, cnt, WcV, WcE, bc, idc);

    // ===== stream 0: reduceU =====
    csr_reduceU_kernel<<<seg_grid(NE), 256>>>(ib + IR_D, ib + IG_D, invDV, vfeat, U, dw, NE);
    cudaEventRecord(g_eU, 0);

    // s0: A1 = U @ W1v.T
    gemm_kernel<<<GG, 256>>>(U, nullptr, psi1_W, 256, nullptr, nullptr, nullptr, nullptr, A1, NE, 0);

    // s2: A2 = dw .* (efeat @ W1e.T + b1)   (needs dw)
    cudaStreamWaitEvent(g_s2, g_eU, 0);
    gemm_kernel<<<GG, 256, 0, g_s2>>>(efeat, nullptr, psi1_W + 128, 256, psi1_b, dw, nullptr, nullptr, A2b, NE, 0);
    cudaEventRecord(g_eA2, g_s2);
    // s2: P1 = idc .* (efeat @ WcE.T + bc)
    gemm_kernel<<<GG, 256, 0, g_s2>>>(efeat, nullptr, WcE, 128, bc, idc, nullptr, nullptr, P1, NE, 0);
    cudaEventRecord(g_eP1, g_s2);

    // ===== stream 1 (chain B reduces + P gemm) =====
    csr_reduce_kernel<<<seg_grid(NN), 256, 0, g_s1>>>(ib + IR_S, ib + IG_S, efeat, v2, NN, 0);
    csr_reduceW_kernel<<<seg_grid(NN), 256, 0, g_s1>>>(ib + IR_V, ib + IG_V, wV, v2, v3, NN);
    csr_reduce_kernel<<<seg_grid(NE), 256, 0, g_s1>>>(ib + IR_D, ib + IG_D, v3, e2acc, NE, 0);
    cudaStreamWaitEvent(g_s1, g_eP1, 0);
    // P = e2acc @ We.T + P1
    gemm_kernel<<<GG, 256, 0, g_s1>>>(e2acc, nullptr, We, 128, nullptr, nullptr, nullptr, P1, P, NE, 0);
    cudaEventRecord(g_eB, g_s1);

    // ===== stream 0 (critical path) =====
    // emA = emat @ (A1 + A2)
    cudaStreamWaitEvent(0, g_eA2, 0);
    csr_reduceW2_kernel<<<seg_grid(NE), 256>>>(ib + IR_E, ib + IG_E, wE, A1, A2b, emA, NE);
    // ew = (emA + efeat) @ Wv.T
    gemm_kernel<<<GG, 256>>>(emA, efeat, Wv, 128, nullptr, nullptr, nullptr, nullptr, ew, NE, 0);
    // vout[n] = relu( sum_{inc of n} ew[dst] )
    csr_reduce_kernel<<<seg_grid(NN), 256>>>(ib + IR_S, ib + IG_S, ew, vout, NN, 1);
    // T[e] = sum_{inc of e} vout[src]
    csr_reduce_kernel<<<seg_grid(NE), 256>>>(ib + IR_D, ib + IG_D, vout, T, NE, 0);
    // eout = relu( invDE .* (T @ WcV.T) + P )
    cudaStreamWaitEvent(0, g_eB, 0);
    gemm_kernel<<<GG, 256>>>(T, nullptr, WcV, 128, nullptr, invDE, nullptr, P, eout, NE, 1);
}

// round 16
// speedup vs baseline: 1.2228x; 1.0170x over previous
#include <cuda_runtime.h>
#include <cuda_bf16.h>
#include <cstddef>

// ---------------- problem constants ----------------
#define NN 50000
#define NE 10000
#define DD 128
#define NNZI 400000
#define NNZE 80000
#define NNZV 400000
#define TOT3 (NNZI + NNZV + NNZE)       // 880,000 (S + V + E)

static const size_t ND = (size_t)NN * DD;   // 6,400,000
static const size_t ED = (size_t)NE * DD;   // 1,280,000

// ---------------- float scratch (no zeroing needed) ----------------
static const size_t OFF_U     = 0;          // E
static const size_t OFF_T     = ED;         // E
static const size_t OFF_EMA   = 2*ED;       // E
static const size_t OFF_A1    = 3*ED;       // E
static const size_t OFF_A2    = 4*ED;       // E
static const size_t OFF_EW    = 5*ED;       // E
static const size_t OFF_E2ACC = 6*ED;       // E
static const size_t OFF_P1    = 7*ED;       // E
static const size_t OFF_P     = 8*ED;       // E
static const size_t OFF_V2    = 9*ED;       // N
static const size_t OFF_V3    = 9*ED + ND;  // N
static const size_t OFF_DW    = 9*ED + 2*ND;            // NE
static const size_t OFF_CNT   = 9*ED + 2*ND + NE;       // NE
static const size_t OFF_IDC   = 9*ED + 2*ND + 2*NE;     // NE  (invDE*cnt)
static const size_t OFF_WV    = 9*ED + 2*ND + 3*NE;     // NNZV (reordered vmat vals)
static const size_t OFF_WE    = OFF_WV + NNZV;          // NNZE (reordered emat vals)
static const size_t OFF_WCV   = OFF_WE + NNZE;          // 16384 (We@W2v, [n][k])
static const size_t OFF_WCE   = OFF_WCV + 16384;        // 16384 (We@W2e, [n][k])
static const size_t OFF_BC    = OFF_WCE + 16384;        // 128   (We@b2)
#define SCRATCH_TOTAL (9*1280000ull + 2*6400000ull + 3*10000ull + 400000ull + 80000ull + 33024ull)
__device__ float g_scratch[SCRATCH_TOTAL];

// ---------------- int scratch: CSR structures ----------------
#define IC_CD 0
#define IC_CS (IC_CD + NE)
#define IC_CV (IC_CS + NN)
#define IC_CE (IC_CV + NN)
#define ICNT_LEN (IC_CE + NE)                 // 120,000
#define IR_D (ICNT_LEN)
#define IR_S (IR_D + NE + 1)
#define IR_V (IR_S + NN + 1)
#define IR_E (IR_V + NN + 1)
#define IQ_D (IR_E + NE + 1)
#define IQ_S (IQ_D + NE)
#define IQ_V (IQ_S + NN)
#define IQ_E (IQ_V + NN)
#define IG_D (IQ_E + NE)
#define IG_S (IG_D + NNZI)
#define IG_V (IG_S + NNZI)
#define IG_E (IG_V + NNZV)
#define ITOTAL (IG_E + NNZE)
__device__ int g_iscr[ITOTAL];

typedef unsigned long long u64;

__device__ __forceinline__ void fma2(u64& d, u64 a, u64 b) {
    asm("fma.rn.f32x2 %0, %1, %2, %0;" : "+l"(d) : "l"(a), "l"(b));
}
__device__ __forceinline__ u64 dup2(float v) {
    u64 r;
    asm("mov.b64 %0, {%1,%1};" : "=l"(r) : "r"(__float_as_uint(v)));
    return r;
}
__device__ __forceinline__ float lo32(u64 v) { return __uint_as_float((unsigned)v); }
__device__ __forceinline__ float hi32(u64 v) { return __uint_as_float((unsigned)(v >> 32)); }

// ================= CSR build: D part (critical path) =================
__global__ void histD_kernel(const int* __restrict__ inc_dst, int* __restrict__ ib) {
    int i = blockIdx.x * blockDim.x + threadIdx.x;
    if (i < NNZI) atomicAdd(&ib[IC_CD + inc_dst[i]], 1);
}

// 1 block: exclusive scan of D counts -> IR_D, IQ_D, cnt(float), idc=invDE*cnt
__global__ __launch_bounds__(1024) void scanD_kernel(int* __restrict__ ib,
                                                     const float* __restrict__ invDE,
                                                     float* __restrict__ cntf,
                                                     float* __restrict__ idc) {
    __shared__ int part[1024];
    int t = threadIdx.x;
    const int n = NE;
    const int* cnt = ib + IC_CD;
    int* rs  = ib + IR_D;
    int* cur = ib + IQ_D;
    int chunk = (n + 1023) >> 10;
    int s0 = t * chunk, s = 0;
    for (int k = 0; k < chunk; k++) { int idx = s0 + k; if (idx < n) s += cnt[idx]; }
    part[t] = s;
    __syncthreads();
    for (int off = 1; off < 1024; off <<= 1) {
        int v = (t >= off) ? part[t - off] : 0;
        __syncthreads();
        part[t] += v;
        __syncthreads();
    }
    int run = part[t] - s;
    for (int k = 0; k < chunk; k++) {
        int idx = s0 + k;
        if (idx < n) {
            int c = cnt[idx];
            rs[idx] = run; cur[idx] = run;
            float fc = (float)c;
            cntf[idx] = fc;
            idc[idx] = invDE[idx] * fc;
            run += c;
        }
    }
    if (t == 1023) rs[n] = part[1023];
}

__global__ void permuteD_kernel(const int* __restrict__ inc_dst, const int* __restrict__ inc_src,
                                int* __restrict__ ib) {
    int i = blockIdx.x * blockDim.x + threadIdx.x;
    if (i < NNZI) {
        int p = atomicAdd(&ib[IQ_D + inc_dst[i]], 1);
        ib[IG_D + p] = inc_src[i];
    }
}

// ================= CSR build: S/V/E part (side stream) =================
__global__ void hist3_kernel(const int* __restrict__ inc_src,
                             const int* __restrict__ vmat_rows, const int* __restrict__ emat_rows,
                             int* __restrict__ ib) {
    int i = blockIdx.x * blockDim.x + threadIdx.x;
    if (i < NNZI)               atomicAdd(&ib[IC_CS + inc_src[i]], 1);
    else if (i < NNZI + NNZV)   atomicAdd(&ib[IC_CV + vmat_rows[i - NNZI]], 1);
    else if (i < TOT3)          atomicAdd(&ib[IC_CE + emat_rows[i - NNZI - NNZV]], 1);
}

__global__ __launch_bounds__(1024) void scan3_kernel(int* __restrict__ ib) {
    __shared__ int part[1024];
    int b = blockIdx.x, t = threadIdx.x;
    int cofs, n, rofs, qofs;
    if (b == 0)      { cofs = IC_CS; n = NN; rofs = IR_S; qofs = IQ_S; }
    else if (b == 1) { cofs = IC_CV; n = NN; rofs = IR_V; qofs = IQ_V; }
    else             { cofs = IC_CE; n = NE; rofs = IR_E; qofs = IQ_E; }
    const int* cnt = ib + cofs;
    int* rs  = ib + rofs;
    int* cur = ib + qofs;
    int chunk = (n + 1023) >> 10;
    int s0 = t * chunk, s = 0;
    for (int k = 0; k < chunk; k++) { int idx = s0 + k; if (idx < n) s += cnt[idx]; }
    part[t] = s;
    __syncthreads();
    for (int off = 1; off < 1024; off <<= 1) {
        int v = (t >= off) ? part[t - off] : 0;
        __syncthreads();
        part[t] += v;
        __syncthreads();
    }
    int run = part[t] - s;
    for (int k = 0; k < chunk; k++) {
        int idx = s0 + k;
        if (idx < n) { int c = cnt[idx]; rs[idx] = run; cur[idx] = run; run += c; }
    }
    if (t == 1023) rs[n] = part[1023];
}

__global__ void permute3_kernel(const int* __restrict__ inc_dst, const int* __restrict__ inc_src,
                                const int* __restrict__ vmat_rows, const int* __restrict__ vmat_cols,
                                const float* __restrict__ vmat_vals,
                                const int* __restrict__ emat_rows, const int* __restrict__ emat_cols,
                                const float* __restrict__ emat_vals,
                                int* __restrict__ ib, float* __restrict__ wV, float* __restrict__ wE) {
    int i = blockIdx.x * blockDim.x + threadIdx.x;
    if (i < NNZI) {
        int p = atomicAdd(&ib[IQ_S + inc_src[i]], 1);
        ib[IG_S + p] = inc_dst[i];
    } else if (i < NNZI + NNZV) {
        int j = i - NNZI;
        int p = atomicAdd(&ib[IQ_V + vmat_rows[j]], 1);
        ib[IG_V + p] = vmat_cols[j];
        wV[p] = vmat_vals[j];
    } else if (i < TOT3) {
        int j = i - NNZI - NNZV;
        int p = atomicAdd(&ib[IQ_E + emat_rows[j]], 1);
        ib[IG_E + p] = emat_cols[j];
        wE[p] = emat_vals[j];
    }
}

// ============ weight composition: WcV = We@W2v, WcE = We@W2e, bc = We@b2 ========
__global__ void wcomp_kernel(const float* __restrict__ We, const float* __restrict__ psi2_W,
                             const float* __restrict__ psi2_b,
                             float* __restrict__ WcV, float* __restrict__ WcE,
                             float* __restrict__ bc) {
    int i = blockIdx.x * blockDim.x + threadIdx.x;
    if (i < 16384) {
        int n = i >> 7, k = i & 127;
        float s = 0.f;
#pragma unroll 8
        for (int j = 0; j < 128; j++) s = fmaf(We[n * 128 + j], psi2_W[j * 256 + k], s);
        WcV[n * 128 + k] = s;
    } else if (i < 32768) {
        int t = i - 16384;
        int n = t >> 7, k = t & 127;
        float s = 0.f;
#pragma unroll 8
        for (int j = 0; j < 128; j++) s = fmaf(We[n * 128 + j], psi2_W[j * 256 + 128 + k], s);
        WcE[n * 128 + k] = s;
    } else if (i < 32896) {
        int n = i - 32768;
        float s = 0.f;
#pragma unroll 8
        for (int j = 0; j < 128; j++) s = fmaf(We[n * 128 + j], psi2_b[j], s);
        bc[n] = s;
    }
}

// ================= CSR segment reduce (warp/segment, MLP=4) =================
__global__ __launch_bounds__(256) void csr_reduce_kernel(
    const int* __restrict__ rs, const int* __restrict__ g,
    const float* __restrict__ src, float* __restrict__ dst,
    int nseg, int doRelu) {
    int w = (blockIdx.x * blockDim.x + threadIdx.x) >> 5;
    int lane = threadIdx.x & 31;
    if (w >= nseg) return;
    int j = rs[w], end = rs[w + 1];
    float ax = 0.f, ay = 0.f, az = 0.f, aw = 0.f;
    float bx = 0.f, by = 0.f, bz = 0.f, bw = 0.f;
    for (; j + 4 <= end; j += 4) {
        int g0 = __ldg(g + j), g1 = __ldg(g + j + 1);
        int g2 = __ldg(g + j + 2), g3 = __ldg(g + j + 3);
        float4 x0 = __ldg((const float4*)(src + (size_t)g0 * DD) + lane);
        float4 x1 = __ldg((const float4*)(src + (size_t)g1 * DD) + lane);
        float4 x2 = __ldg((const float4*)(src + (size_t)g2 * DD) + lane);
        float4 x3 = __ldg((const float4*)(src + (size_t)g3 * DD) + lane);
        ax += x0.x + x1.x; ay += x0.y + x1.y; az += x0.z + x1.z; aw += x0.w + x1.w;
        bx += x2.x + x3.x; by += x2.y + x3.y; bz += x2.z + x3.z; bw += x2.w + x3.w;
    }
    for (; j < end; j++) {
        int g0 = __ldg(g + j);
        float4 x0 = __ldg((const float4*)(src + (size_t)g0 * DD) + lane);
        ax += x0.x; ay += x0.y; az += x0.z; aw += x0.w;
    }
    ax += bx; ay += by; az += bz; aw += bw;
    if (doRelu) {
        ax = fmaxf(ax, 0.f); ay = fmaxf(ay, 0.f);
        az = fmaxf(az, 0.f); aw = fmaxf(aw, 0.f);
    }
    *((float4*)(dst + (size_t)w * DD) + lane) = make_float4(ax, ay, az, aw);
}

__global__ __launch_bounds__(256) void csr_reduceW_kernel(
    const int* __restrict__ rs, const int* __restrict__ g, const float* __restrict__ wgt,
    const float* __restrict__ src, float* __restrict__ dst, int nseg) {
    int w = (blockIdx.x * blockDim.x + threadIdx.x) >> 5;
    int lane = threadIdx.x & 31;
    if (w >= nseg) return;
    int j = rs[w], end = rs[w + 1];
    float ax = 0.f, ay = 0.f, az = 0.f, aw = 0.f;
    float bx = 0.f, by = 0.f, bz = 0.f, bw = 0.f;
    for (; j + 4 <= end; j += 4) {
        int g0 = __ldg(g + j), g1 = __ldg(g + j + 1);
        int g2 = __ldg(g + j + 2), g3 = __ldg(g + j + 3);
        float v0 = __ldg(wgt + j), v1 = __ldg(wgt + j + 1);
        float v2 = __ldg(wgt + j + 2), v3 = __ldg(wgt + j + 3);
        float4 x0 = __ldg((const float4*)(src + (size_t)g0 * DD) + lane);
        float4 x1 = __ldg((const float4*)(src + (size_t)g1 * DD) + lane);
        float4 x2 = __ldg((const float4*)(src + (size_t)g2 * DD) + lane);
        float4 x3 = __ldg((const float4*)(src + (size_t)g3 * DD) + lane);
        ax = fmaf(x0.x, v0, fmaf(x1.x, v1, ax));
        ay = fmaf(x0.y, v0, fmaf(x1.y, v1, ay));
        az = fmaf(x0.z, v0, fmaf(x1.z, v1, az));
        aw = fmaf(x0.w, v0, fmaf(x1.w, v1, aw));
        bx = fmaf(x2.x, v2, fmaf(x3.x, v3, bx));
        by = fmaf(x2.y, v2, fmaf(x3.y, v3, by));
        bz = fmaf(x2.z, v2, fmaf(x3.z, v3, bz));
        bw = fmaf(x2.w, v2, fmaf(x3.w, v3, bw));
    }
    for (; j < end; j++) {
        int g0 = __ldg(g + j);
        float v0 = __ldg(wgt + j);
        float4 x0 = __ldg((const float4*)(src + (size_t)g0 * DD) + lane);
        ax = fmaf(x0.x, v0, ax); ay = fmaf(x0.y, v0, ay);
        az = fmaf(x0.z, v0, az); aw = fmaf(x0.w, v0, aw);
    }
    ax += bx; ay += by; az += bz; aw += bw;
    *((float4*)(dst + (size_t)w * DD) + lane) = make_float4(ax, ay, az, aw);
}

// dual-source weighted reduce: dst[s,:] = sum_j wgt[j] * (srcA[g[j],:] + srcB[g[j],:])
__global__ __launch_bounds__(256) void csr_reduceW2_kernel(
    const int* __restrict__ rs, const int* __restrict__ g, const float* __restrict__ wgt,
    const float* __restrict__ srcA, const float* __restrict__ srcB,
    float* __restrict__ dst, int nseg) {
    int w = (blockIdx.x * blockDim.x + threadIdx.x) >> 5;
    int lane = threadIdx.x & 31;
    if (w >= nseg) return;
    int j = rs[w], end = rs[w + 1];
    float ax = 0.f, ay = 0.f, az = 0.f, aw = 0.f;
    for (; j + 2 <= end; j += 2) {
        int g0 = __ldg(g + j), g1 = __ldg(g + j + 1);
        float v0 = __ldg(wgt + j), v1 = __ldg(wgt + j + 1);
        float4 a0 = __ldg((const float4*)(srcA + (size_t)g0 * DD) + lane);
        float4 b0 = __ldg((const float4*)(srcB + (size_t)g0 * DD) + lane);
        float4 a1 = __ldg((const float4*)(srcA + (size_t)g1 * DD) + lane);
        float4 b1 = __ldg((const float4*)(srcB + (size_t)g1 * DD) + lane);
        ax = fmaf(a0.x + b0.x, v0, fmaf(a1.x + b1.x, v1, ax));
        ay = fmaf(a0.y + b0.y, v0, fmaf(a1.y + b1.y, v1, ay));
        az = fmaf(a0.z + b0.z, v0, fmaf(a1.z + b1.z, v1, az));
        aw = fmaf(a0.w + b0.w, v0, fmaf(a1.w + b1.w, v1, aw));
    }
    if (j < end) {
        int g0 = __ldg(g + j);
        float v0 = __ldg(wgt + j);
        float4 a0 = __ldg((const float4*)(srcA + (size_t)g0 * DD) + lane);
        float4 b0 = __ldg((const float4*)(srcB + (size_t)g0 * DD) + lane);
        ax = fmaf(a0.x + b0.x, v0, ax); ay = fmaf(a0.y + b0.y, v0, ay);
        az = fmaf(a0.z + b0.z, v0, az); aw = fmaf(a0.w + b0.w, v0, aw);
    }
    *((float4*)(dst + (size_t)w * DD) + lane) = make_float4(ax, ay, az, aw);
}

__global__ __launch_bounds__(256) void csr_reduceU_kernel(
    const int* __restrict__ rs, const int* __restrict__ g,
    const float* __restrict__ invDV, const float* __restrict__ vfeat,
    float* __restrict__ U, float* __restrict__ dw, int nseg) {
    int w = (blockIdx.x * blockDim.x + threadIdx.x) >> 5;
    int lane = threadIdx.x & 31;
    if (w >= nseg) return;
    int j = rs[w], end = rs[w + 1];
    float ax = 0.f, ay = 0.f, az = 0.f, aw = 0.f, ws = 0.f;
    float bx = 0.f, by = 0.f, bz = 0.f, bw = 0.f;
    for (; j + 4 <= end; j += 4) {
        int g0 = __ldg(g + j), g1 = __ldg(g + j + 1);
        int g2 = __ldg(g + j + 2), g3 = __ldg(g + j + 3);
        float v0 = __ldg(invDV + g0), v1 = __ldg(invDV + g1);
        float v2 = __ldg(invDV + g2), v3 = __ldg(invDV + g3);
        float4 x0 = __ldg((const float4*)(vfeat + (size_t)g0 * DD) + lane);
        float4 x1 = __ldg((const float4*)(vfeat + (size_t)g1 * DD) + lane);
        float4 x2 = __ldg((const float4*)(vfeat + (size_t)g2 * DD) + lane);
        float4 x3 = __ldg((const float4*)(vfeat + (size_t)g3 * DD) + lane);
        ax = fmaf(x0.x, v0, fmaf(x1.x, v1, ax));
        ay = fmaf(x0.y, v0, fmaf(x1.y, v1, ay));
        az = fmaf(x0.z, v0, fmaf(x1.z, v1, az));
        aw = fmaf(x0.w, v0, fmaf(x1.w, v1, aw));
        bx = fmaf(x2.x, v2, fmaf(x3.x, v3, bx));
        by = fmaf(x2.y, v2, fmaf(x3.y, v3, by));
        bz = fmaf(x2.z, v2, fmaf(x3.z, v3, bz));
        bw = fmaf(x2.w, v2, fmaf(x3.w, v3, bw));
        ws += (v0 + v1) + (v2 + v3);
    }
    for (; j < end; j++) {
        int g0 = __ldg(g + j);
        float v0 = __ldg(invDV + g0);
        float4 x0 = __ldg((const float4*)(vfeat + (size_t)g0 * DD) + lane);
        ax = fmaf(x0.x, v0, ax); ay = fmaf(x0.y, v0, ay);
        az = fmaf(x0.z, v0, az); aw = fmaf(x0.w, v0, aw);
        ws += v0;
    }
    ax += bx; ay += by; az += bz; aw += bw;
    *((float4*)(U + (size_t)w * DD) + lane) = make_float4(ax, ay, az, aw);
    if (lane == 0) dw[w] = ws;
}

// ================= GEMM (verbatim R8): C = post( (A+A2) @ W.T ), f32x2 math ====
// post: v = (acc + bias[n] + Cprev[m,n]) * rowScale[m] + Cadd[m,n]; optional relu.
__global__ __launch_bounds__(256) void gemm_kernel(
    const float* __restrict__ A, const float* __restrict__ A2,
    const float* __restrict__ W, int ldW,
    const float* __restrict__ bias, const float* __restrict__ rowScale,
    const float* __restrict__ Cprev, const float* __restrict__ Cadd,
    float* __restrict__ C, int M, int doRelu) {
    __shared__ float As[16][64];
    __shared__ float Bs[16][128];
    int m0 = blockIdx.x * 64;
    int tid = threadIdx.x;
    int tm = tid >> 5;
    int tn = tid & 31;

    u64 acc[4][4];
#pragma unroll
    for (int p = 0; p < 4; p++)
#pragma unroll
        for (int j = 0; j < 4; j++) acc[p][j] = 0ull;

    int ra = tid >> 2;
    int ka = (tid & 3) * 4;

    for (int kk = 0; kk < 128; kk += 16) {
        float4 av = make_float4(0.f, 0.f, 0.f, 0.f);
        int gm = m0 + ra;
        if (gm < M) {
            av = *(const float4*)(A + (size_t)gm * DD + kk + ka);
            if (A2) {
                float4 a2 = *(const float4*)(A2 + (size_t)gm * DD + kk + ka);
                av.x += a2.x; av.y += a2.y; av.z += a2.z; av.w += a2.w;
            }
        }
        As[ka + 0][ra] = av.x;
        As[ka + 1][ra] = av.y;
        As[ka + 2][ra] = av.z;
        As[ka + 3][ra] = av.w;
#pragma unroll
        for (int i = 0; i < 2; i++) {
            int idx = tid * 2 + i;
            int n = idx >> 2;
            int kq = (idx & 3) * 4;
            float4 wv = *(const float4*)(W + (size_t)n * ldW + kk + kq);
            Bs[kq + 0][n] = wv.x;
            Bs[kq + 1][n] = wv.y;
            Bs[kq + 2][n] = wv.z;
            Bs[kq + 3][n] = wv.w;
        }
        __syncthreads();
#pragma unroll
        for (int k = 0; k < 16; k++) {
            const u64* ap = (const u64*)&As[k][tm * 8];
            u64 a0 = ap[0], a1 = ap[1], a2 = ap[2], a3 = ap[3];
            float4 bv = *(const float4*)&Bs[k][tn * 4];
            u64 b0 = dup2(bv.x), b1 = dup2(bv.y), b2 = dup2(bv.z), b3 = dup2(bv.w);
            fma2(acc[0][0], a0, b0); fma2(acc[0][1], a0, b1);
            fma2(acc[0][2], a0, b2); fma2(acc[0][3], a0, b3);
            fma2(acc[1][0], a1, b0); fma2(acc[1][1], a1, b1);
            fma2(acc[1][2], a1, b2); fma2(acc[1][3], a1, b3);
            fma2(acc[2][0], a2, b0); fma2(acc[2][1], a2, b1);
            fma2(acc[2][2], a2, b2); fma2(acc[2][3], a2, b3);
            fma2(acc[3][0], a3, b0); fma2(acc[3][1], a3, b1);
            fma2(acc[3][2], a3, b2); fma2(acc[3][3], a3, b3);
        }
        __syncthreads();
    }

    float bvals[4];
#pragma unroll
    for (int j = 0; j < 4; j++) bvals[j] = bias ? bias[tn * 4 + j] : 0.f;

#pragma unroll
    for (int p = 0; p < 4; p++) {
        int mA = m0 + tm * 8 + p * 2;
#pragma unroll
        for (int q = 0; q < 2; q++) {
            int m = mA + q;
            if (m >= M) continue;
            float rs = rowScale ? rowScale[m] : 1.f;
            float4 cp = make_float4(0.f, 0.f, 0.f, 0.f);
            if (Cprev) cp = *(const float4*)(Cprev + (size_t)m * DD + tn * 4);
            float4 ca = make_float4(0.f, 0.f, 0.f, 0.f);
            if (Cadd) ca = *(const float4*)(Cadd + (size_t)m * DD + tn * 4);
            float r0 = q ? hi32(acc[p][0]) : lo32(acc[p][0]);
            float r1 = q ? hi32(acc[p][1]) : lo32(acc[p][1]);
            float r2 = q ? hi32(acc[p][2]) : lo32(acc[p][2]);
            float r3 = q ? hi32(acc[p][3]) : lo32(acc[p][3]);
            float v0 = (r0 + bvals[0] + cp.x) * rs + ca.x;
            float v1 = (r1 + bvals[1] + cp.y) * rs + ca.y;
            float v2 = (r2 + bvals[2] + cp.z) * rs + ca.z;
            float v3 = (r3 + bvals[3] + cp.w) * rs + ca.w;
            if (doRelu) {
                v0 = fmaxf(v0, 0.f); v1 = fmaxf(v1, 0.f);
                v2 = fmaxf(v2, 0.f); v3 = fmaxf(v3, 0.f);
            }
            *(float4*)(C + (size_t)m * DD + tn * 4) = make_float4(v0, v1, v2, v3);
        }
    }
}

// ---------------- host side ----------------
static inline int seg_grid(int nseg) { return (nseg + 7) / 8; }

static cudaStream_t g_s1 = nullptr, g_s2 = nullptr;
static cudaEvent_t g_eFork = nullptr, g_ePD = nullptr, g_eP3 = nullptr,
                   g_eU = nullptr, g_eA2 = nullptr, g_eP1 = nullptr, g_eB = nullptr;

extern "C" void kernel_launch(void* const* d_in, const int* in_sizes, int n_in,
                              void* d_out, int out_size) {
    const float* vfeat   = (const float*)d_in[0];
    const float* efeat   = (const float*)d_in[1];
    const float* invDV   = (const float*)d_in[2];
    const float* invDE   = (const float*)d_in[3];
    const int*   inc_src = (const int*)d_in[4];
    const int*   inc_dst = (const int*)d_in[5];
    const int*   emat_rows = (const int*)d_in[6];
    const int*   emat_cols = (const int*)d_in[7];
    const float* emat_vals = (const float*)d_in[8];
    const int*   vmat_rows = (const int*)d_in[9];
    const int*   vmat_cols = (const int*)d_in[10];
    const float* vmat_vals = (const float*)d_in[11];
    const float* Wv      = (const float*)d_in[12];
    const float* We      = (const float*)d_in[13];
    const float* psi1_W  = (const float*)d_in[14];
    const float* psi1_b  = (const float*)d_in[15];
    const float* psi2_W  = (const float*)d_in[16];
    const float* psi2_b  = (const float*)d_in[17];

    if (!g_s1) {
        cudaStreamCreateWithFlags(&g_s1, cudaStreamNonBlocking);
        cudaStreamCreateWithFlags(&g_s2, cudaStreamNonBlocking);
        cudaEventCreateWithFlags(&g_eFork, cudaEventDisableTiming);
        cudaEventCreateWithFlags(&g_ePD,   cudaEventDisableTiming);
        cudaEventCreateWithFlags(&g_eP3,   cudaEventDisableTiming);
        cudaEventCreateWithFlags(&g_eU,    cudaEventDisableTiming);
        cudaEventCreateWithFlags(&g_eA2,   cudaEventDisableTiming);
        cudaEventCreateWithFlags(&g_eP1,   cudaEventDisableTiming);
        cudaEventCreateWithFlags(&g_eB,    cudaEventDisableTiming);
    }

    float* base = nullptr;
    cudaGetSymbolAddress((void**)&base, g_scratch);
    int* ib = nullptr;
    cudaGetSymbolAddress((void**)&ib, g_iscr);

    float* U     = base + OFF_U;
    float* T     = base + OFF_T;
    float* emA   = base + OFF_EMA;
    float* A1    = base + OFF_A1;
    float* A2b   = base + OFF_A2;
    float* ew    = base + OFF_EW;
    float* e2acc = base + OFF_E2ACC;
    float* P1    = base + OFF_P1;
    float* P     = base + OFF_P;
    float* v2    = base + OFF_V2;
    float* v3    = base + OFF_V3;
    float* dw    = base + OFF_DW;
    float* cnt   = base + OFF_CNT;
    float* idc   = base + OFF_IDC;
    float* wV    = base + OFF_WV;
    float* wE    = base + OFF_WE;
    float* WcV   = base + OFF_WCV;
    float* WcE   = base + OFF_WCE;
    float* bc    = base + OFF_BC;

    float* vout = (float*)d_out;               // [NN,128]
    float* eout = vout + ND;                   // [NE,128]

    const int GG = (NE + 63) / 64;             // 157

    // ---- fork immediately: side streams start while s0 builds D-CSR ----
    cudaEventRecord(g_eFork, 0);
    cudaStreamWaitEvent(g_s1, g_eFork, 0);
    cudaStreamWaitEvent(g_s2, g_eFork, 0);

    // ===== stream 0: D-CSR build (critical prefix, NNZI only) =====
    cudaMemsetAsync(ib + IC_CD, 0, NE * sizeof(int));
    histD_kernel<<<(NNZI + 255) / 256, 256>>>(inc_dst, ib);
    scanD_kernel<<<1, 1024>>>(ib, invDE, cnt, idc);
    permuteD_kernel<<<(NNZI + 255) / 256, 256>>>(inc_dst, inc_src, ib);
    cudaEventRecord(g_ePD, 0);

    // ===== stream 2: weight composition (no data deps) =====
    wcomp_kernel<<<129, 256, 0, g_s2>>>(We, psi2_W, psi2_b, WcV, WcE, bc);

    // ===== stream 1: S/V/E CSR build =====
    cudaMemsetAsync(ib + IC_CS, 0, (ICNT_LEN - NE) * sizeof(int), g_s1);
    hist3_kernel<<<(TOT3 + 255) / 256, 256, 0, g_s1>>>(inc_src, vmat_rows, emat_rows, ib);
    scan3_kernel<<<3, 1024, 0, g_s1>>>(ib);
    permute3_kernel<<<(TOT3 + 255) / 256, 256, 0, g_s1>>>(inc_dst, inc_src,
                                                          vmat_rows, vmat_cols, vmat_vals,
                                                          emat_rows, emat_cols, emat_vals,
                                                          ib, wV, wE);
    cudaEventRecord(g_eP3, g_s1);

    // ===== stream 0: reduceU + A1 =====
    csr_reduceU_kernel<<<seg_grid(NE), 256>>>(ib + IR_D, ib + IG_D, invDV, vfeat, U, dw, NE);
    cudaEventRecord(g_eU, 0);
    gemm_kernel<<<GG, 256>>>(U, nullptr, psi1_W, 256, nullptr, nullptr, nullptr, nullptr, A1, NE, 0);

    // ===== stream 2: A2 (needs dw), then P1 (needs idc: done before eU) =====
    cudaStreamWaitEvent(g_s2, g_eU, 0);
    gemm_kernel<<<GG, 256, 0, g_s2>>>(efeat, nullptr, psi1_W + 128, 256, psi1_b, dw, nullptr, nullptr, A2b, NE, 0);
    cudaEventRecord(g_eA2, g_s2);
    gemm_kernel<<<GG, 256, 0, g_s2>>>(efeat, nullptr, WcE, 128, bc, idc, nullptr, nullptr, P1, NE, 0);
    cudaEventRecord(g_eP1, g_s2);

    // ===== stream 1: chain-B reduces + P gemm =====
    csr_reduce_kernel<<<seg_grid(NN), 256, 0, g_s1>>>(ib + IR_S, ib + IG_S, efeat, v2, NN, 0);
    csr_reduceW_kernel<<<seg_grid(NN), 256, 0, g_s1>>>(ib + IR_V, ib + IG_V, wV, v2, v3, NN);
    cudaStreamWaitEvent(g_s1, g_ePD, 0);
    csr_reduce_kernel<<<seg_grid(NE), 256, 0, g_s1>>>(ib + IR_D, ib + IG_D, v3, e2acc, NE, 0);
    cudaStreamWaitEvent(g_s1, g_eP1, 0);
    // P = e2acc @ We.T + P1
    gemm_kernel<<<GG, 256, 0, g_s1>>>(e2acc, nullptr, We, 128, nullptr, nullptr, nullptr, P1, P, NE, 0);
    cudaEventRecord(g_eB, g_s1);

    // ===== stream 0 (critical path) =====
    // emA = emat @ (A1 + A2)   (needs IG_E/wE from s1 build, A2 from s2)
    cudaStreamWaitEvent(0, g_eP3, 0);
    cudaStreamWaitEvent(0, g_eA2, 0);
    csr_reduceW2_kernel<<<seg_grid(NE), 256>>>(ib + IR_E, ib + IG_E, wE, A1, A2b, emA, NE);
    // ew = (emA + efeat) @ Wv.T
    gemm_kernel<<<GG, 256>>>(emA, efeat, Wv, 128, nullptr, nullptr, nullptr, nullptr, ew, NE, 0);
    // vout[n] = relu( sum_{inc of n} ew[dst] )
    csr_reduce_kernel<<<seg_grid(NN), 256>>>(ib + IR_S, ib + IG_S, ew, vout, NN, 1);
    // T[e] = sum_{inc of e} vout[src]
    csr_reduce_kernel<<<seg_grid(NE), 256>>>(ib + IR_D, ib + IG_D, vout, T, NE, 0);
    // eout = relu( invDE .* (T @ WcV.T) + P )
    cudaStreamWaitEvent(0, g_eB, 0);
    gemm_kernel<<<GG, 256>>>(T, nullptr, WcV, 128, nullptr, invDE, nullptr, P, eout, NE, 1);
}